// round 15
// baseline (speedup 1.0000x reference)
#include <cuda_runtime.h>
#include <math.h>

#define K_DIM 1000
#define N_DIM 1000
#define M_PTS 900000
#define SENTINEL -9999.0f

typedef unsigned long long u64;

// Scratch grid: packed cells. High 32 bits = (m+1) (scatter order priority,
// last-write-wins like XLA in-order scatter), low 32 bits = float bits of val.
__device__ u64 g_cells[K_DIM * N_DIM];

// ── Packed constant layout (float2 units). f32x2 lanes = neurons (2op, 2op+1),
// weights UNduplicated: every 16B LDC.128 carries 4 distinct weights.
#define P_W1 0
#define P_B1 63
#define P_W2 72
#define P_B2 396
#define P_W3 414
#define P_B3 1062
#define P_W4 1080
#define P_B4 1098
#define P_TOTAL 1100

__constant__ __align__(16) float2 cw[P_TOTAL];
__device__ float2 g_pack[P_TOTAL];

__global__ void pack_kernel(
    const float* __restrict__ w1, const float* __restrict__ b1,
    const float* __restrict__ w2, const float* __restrict__ b2,
    const float* __restrict__ w3, const float* __restrict__ b3,
    const float* __restrict__ w4, const float* __restrict__ b4)
{
    int i = blockIdx.x * blockDim.x + threadIdx.x;
    if (i >= P_TOTAL) return;
    float lo = 0.f, hi = 0.f;
    if (i < P_B1) {
        int f = i / 9, op = i % 9;
        lo = w1[(2 * op) * 7 + f];  hi = w1[(2 * op + 1) * 7 + f];
    } else if (i < P_W2) {
        int op = i - P_B1;
        lo = b1[2 * op];            hi = b1[2 * op + 1];
    } else if (i < P_B2) {
        int j = i - P_W2, ii = j / 18, op = j % 18;
        lo = w2[(2 * op) * 18 + ii]; hi = w2[(2 * op + 1) * 18 + ii];
    } else if (i < P_W3) {
        int op = i - P_B2;
        lo = b2[2 * op];            hi = b2[2 * op + 1];
    } else if (i < P_B3) {
        int j = i - P_W3, ii = j / 18, op = j % 18;
        lo = w3[(2 * op) * 36 + ii]; hi = w3[(2 * op + 1) * 36 + ii];
    } else if (i < P_W4) {
        int op = i - P_B3;
        lo = b3[2 * op];            hi = b3[2 * op + 1];
    } else if (i < P_B4) {
        int op = i - P_W4;
        lo = w4[2 * op];            hi = w4[2 * op + 1];
    } else if (i == P_B4) {
        lo = b4[0];                 hi = 0.f;
    }
    g_pack[i] = make_float2(lo, hi);
}

// Vectorized clear: 2 cells (16B) per thread.
__global__ void init_cells(void) {
    int i = blockIdx.x * blockDim.x + threadIdx.x;
    if (i < (K_DIM * N_DIM) / 2)
        *reinterpret_cast<ulonglong2*>(&g_cells[2 * i]) = make_ulonglong2(0ull, 0ull);
}
__global__ void init_out(float* out) {
    int i = blockIdx.x * blockDim.x + threadIdx.x;
    if (i < N_DIM) out[K_DIM + i] = -INFINITY;  // col_max accumulators
}

__device__ __forceinline__ u64 fma2(u64 a, u64 b, u64 c) {
    u64 d;
    asm("fma.rn.f32x2 %0, %1, %2, %3;" : "=l"(d) : "l"(a), "l"(b), "l"(c));
    return d;
}
__device__ __forceinline__ u64 relu2(u64 a) {
    u64 r;
    asm("{\n\t.reg .f32 l, h;\n\t"
        "mov.b64 {l, h}, %1;\n\t"
        "max.f32 l, l, 0f00000000;\n\t"
        "max.f32 h, h, 0f00000000;\n\t"
        "mov.b64 %0, {l, h};\n\t}" : "=l"(r) : "l"(a));
    return r;
}
__device__ __forceinline__ u64 dupf(float v) {
    u64 r;
    asm("mov.b64 %0, {%1, %1};" : "=l"(r) : "f"(v));
    return r;
}
__device__ __forceinline__ u64 dup_lo(u64 p) {
    u64 r;
    asm("{\n\t.reg .f32 l, h;\n\tmov.b64 {l, h}, %1;\n\tmov.b64 %0, {l, l};\n\t}"
        : "=l"(r) : "l"(p));
    return r;
}
__device__ __forceinline__ u64 dup_hi(u64 p) {
    u64 r;
    asm("{\n\t.reg .f32 l, h;\n\tmov.b64 {l, h}, %1;\n\tmov.b64 %0, {h, h};\n\t}"
        : "=l"(r) : "l"(p));
    return r;
}
__device__ __forceinline__ float hadd2(u64 p) {
    float r;
    asm("{\n\t.reg .f32 l, h;\n\tmov.b64 {l, h}, %1;\n\tadd.f32 %0, l, h;\n\t}"
        : "=f"(r) : "l"(p));
    return r;
}
__device__ __forceinline__ u64 mk64(unsigned lo, unsigned hi) {
    return ((u64)hi << 32) | (u64)lo;
}

// ONE point per thread; f32x2 lanes = two adjacent neurons. 64-thread blocks:
// no smem/syncthreads in this kernel, so block size only changes occupancy
// packing — at 77 regs, 13 CTAs/SM = 26 warps (vs 24 at 128-thr blocks) and
// finer tail balancing across 148 SMs. Kernel body identical to r10.
__global__ __launch_bounds__(64, 5) void mlp_scatter_kernel(
    const float* __restrict__ xin, const int* __restrict__ tind)
{
    int m = blockIdx.x * 64 + threadIdx.x;
    if (m >= M_PTS) return;

    const u64* cv = reinterpret_cast<const u64*>(cw);

    // Inputs: scalar per feature, duplicated into both lanes.
    u64 xd[7];
    #pragma unroll
    for (int f = 0; f < 7; ++f)
        xd[f] = dupf(xin[f * M_PTS + m]);

    // ── Layer 1: 7 -> 18 (9 neuron pairs)
    u64 h1[9];
    #pragma unroll
    for (int op = 0; op < 9; ++op) {
        u64 a = cv[P_B1 + op];
        #pragma unroll
        for (int f = 0; f < 7; ++f)
            a = fma2(cv[P_W1 + f * 9 + op], xd[f], a);
        h1[op] = relu2(a);
    }

    // ── Layer 2: 18 -> 36 (18 neuron pairs), i-outer outer-product.
    u64 a2[18];
    #pragma unroll
    for (int op = 0; op < 18; ++op) a2[op] = cv[P_B2 + op];
    #pragma unroll
    for (int ip = 0; ip < 9; ++ip) {
        u64 p = h1[ip];
        #pragma unroll
        for (int half = 0; half < 2; ++half) {
            u64 d = half ? dup_hi(p) : dup_lo(p);
            int i = 2 * ip + half;
            #pragma unroll
            for (int op = 0; op < 18; op += 2) {
                uint4 q = *reinterpret_cast<const uint4*>(&cw[P_W2 + i * 18 + op]);
                a2[op]     = fma2(mk64(q.x, q.y), d, a2[op]);
                a2[op + 1] = fma2(mk64(q.z, q.w), d, a2[op + 1]);
            }
        }
    }
    #pragma unroll
    for (int op = 0; op < 18; ++op) a2[op] = relu2(a2[op]);

    // ── Layer 3+4 fused, single pass.
    u64 v = cv[P_B4];   // (b4, 0): final = lo + hi
    u64 c[18];
    #pragma unroll
    for (int op = 0; op < 18; ++op) c[op] = cv[P_B3 + op];
    #pragma unroll
    for (int ih = 0; ih < 18; ++ih) {
        u64 p = a2[ih];
        #pragma unroll
        for (int half = 0; half < 2; ++half) {
            u64 d = half ? dup_hi(p) : dup_lo(p);
            int i = 2 * ih + half;
            #pragma unroll
            for (int op = 0; op < 18; op += 2) {
                uint4 q = *reinterpret_cast<const uint4*>(&cw[P_W3 + i * 18 + op]);
                c[op]     = fma2(mk64(q.x, q.y), d, c[op]);
                c[op + 1] = fma2(mk64(q.z, q.w), d, c[op + 1]);
            }
        }
    }
    #pragma unroll
    for (int op = 0; op < 18; ++op)
        v = fma2(cv[P_W4 + op], relu2(c[op]), v);

    float val = hadd2(v);

    int r = tind[m];
    int cc = tind[M_PTS + m];
    atomicMax(&g_cells[r * N_DIM + cc],
              (((u64)(unsigned)(m + 1)) << 32) | (u64)__float_as_uint(val));
}

__device__ __forceinline__ float cell_val(u64 k) {
    return (k == 0ull) ? SENTINEL : __uint_as_float((unsigned)(k & 0xFFFFFFFFull));
}

__global__ void row_max_kernel(float* out) {
    int i = blockIdx.x;
    __shared__ float red[256];
    float mx = SENTINEL;
    #pragma unroll
    for (int j = threadIdx.x; j < N_DIM; j += 256)
        mx = fmaxf(mx, cell_val(g_cells[i * N_DIM + j]));
    red[threadIdx.x] = mx;
    __syncthreads();
    #pragma unroll
    for (int s2 = 128; s2 > 0; s2 >>= 1) {
        if (threadIdx.x < s2)
            red[threadIdx.x] = fmaxf(red[threadIdx.x], red[threadIdx.x + s2]);
        __syncthreads();
    }
    if (threadIdx.x == 0) out[i] = red[0];
}

// Order-preserving float atomic max (mixed signs; accumulator init -inf).
__device__ __forceinline__ void atomicMaxFloat(float* addr, float val) {
    if (val >= 0.0f) atomicMax((int*)addr, __float_as_int(val));
    else             atomicMin((unsigned int*)addr, __float_as_uint(val));
}

// blockDim (64,4): 64 cols wide, 64-row strip per blockIdx.y -> 256 blocks.
__global__ void col_max_kernel(float* out) {
    int j = blockIdx.x * 64 + threadIdx.x;
    float mx = SENTINEL;
    if (j < N_DIM) {
        int r0 = blockIdx.y * 64;
        int r1 = min(r0 + 64, K_DIM);
        for (int r = r0 + threadIdx.y; r < r1; r += 4)
            mx = fmaxf(mx, cell_val(g_cells[r * N_DIM + j]));
    }
    __shared__ float red[4][64];
    red[threadIdx.y][threadIdx.x] = mx;
    __syncthreads();
    if (threadIdx.y == 0 && j < N_DIM) {
        float m2 = fmaxf(fmaxf(red[0][threadIdx.x], red[1][threadIdx.x]),
                         fmaxf(red[2][threadIdx.x], red[3][threadIdx.x]));
        atomicMaxFloat(&out[K_DIM + j], m2);
    }
}

extern "C" void kernel_launch(void* const* d_in, const int* in_sizes, int n_in,
                              void* d_out, int out_size) {
    const float* xin = (const float*)d_in[0];
    // d_in[1] = T_out (zeros, unused)
    const int*   tind = (const int*)d_in[2];
    const float* w1 = (const float*)d_in[3];
    const float* b1 = (const float*)d_in[4];
    const float* w2 = (const float*)d_in[5];
    const float* b2 = (const float*)d_in[6];
    const float* w3 = (const float*)d_in[7];
    const float* b3 = (const float*)d_in[8];
    const float* w4 = (const float*)d_in[9];
    const float* b4 = (const float*)d_in[10];
    float* out = (float*)d_out;

    // 1) pack neuron-paired weights into staging buffer
    pack_kernel<<<(P_TOTAL + 255) / 256, 256>>>(w1, b1, w2, b2, w3, b3, w4, b4);

    // 2) D2D async copy into constant memory (graph-capturable memcpy node)
    void* pack_addr = nullptr;
    cudaGetSymbolAddress(&pack_addr, g_pack);
    cudaMemcpyToSymbolAsync(cw, pack_addr, sizeof(float2) * P_TOTAL, 0,
                            cudaMemcpyDeviceToDevice, 0);

    // 3) inits (kernels 2 and 3 -> MLP stays the 4th kernel = ncu capture slot)
    init_cells<<<(K_DIM * N_DIM / 2 + 255) / 256, 256>>>();
    init_out<<<(N_DIM + 255) / 256, 256>>>(out);

    // 4) MLP + scatter: ONE point per thread, 64-thread blocks
    mlp_scatter_kernel<<<(M_PTS + 63) / 64, 64>>>(xin, tind);

    // 5) reductions
    row_max_kernel<<<K_DIM, 256>>>(out);
    dim3 cb(64, 4), cg(16, 16);
    col_max_kernel<<<cg, cb>>>(out);
}

// round 16
// speedup vs baseline: 1.5671x; 1.5671x over previous
#include <cuda_runtime.h>
#include <math.h>

#define K_DIM 1000
#define N_DIM 1000
#define M_PTS 900000
#define SENTINEL -9999.0f

typedef unsigned long long u64;

// Scratch grid: packed cells. High 32 bits = (m+1) (scatter order priority,
// last-write-wins like XLA in-order scatter), low 32 bits = float bits of val.
__device__ u64 g_cells[K_DIM * N_DIM];

// ── Packed constant layout (float2 units). f32x2 lanes = neurons (2op, 2op+1),
// weights UNduplicated: every 16B LDC.128 carries 4 distinct weights.
#define P_W1 0
#define P_B1 63
#define P_W2 72
#define P_B2 396
#define P_W3 414
#define P_B3 1062
#define P_W4 1080
#define P_B4 1098
#define P_TOTAL 1100

__constant__ __align__(16) float2 cw[P_TOTAL];
__device__ float2 g_pack[P_TOTAL];

__global__ void pack_kernel(
    const float* __restrict__ w1, const float* __restrict__ b1,
    const float* __restrict__ w2, const float* __restrict__ b2,
    const float* __restrict__ w3, const float* __restrict__ b3,
    const float* __restrict__ w4, const float* __restrict__ b4)
{
    int i = blockIdx.x * blockDim.x + threadIdx.x;
    if (i >= P_TOTAL) return;
    float lo = 0.f, hi = 0.f;
    if (i < P_B1) {
        int f = i / 9, op = i % 9;
        lo = w1[(2 * op) * 7 + f];  hi = w1[(2 * op + 1) * 7 + f];
    } else if (i < P_W2) {
        int op = i - P_B1;
        lo = b1[2 * op];            hi = b1[2 * op + 1];
    } else if (i < P_B2) {
        int j = i - P_W2, ii = j / 18, op = j % 18;
        lo = w2[(2 * op) * 18 + ii]; hi = w2[(2 * op + 1) * 18 + ii];
    } else if (i < P_W3) {
        int op = i - P_B2;
        lo = b2[2 * op];            hi = b2[2 * op + 1];
    } else if (i < P_B3) {
        int j = i - P_W3, ii = j / 18, op = j % 18;
        lo = w3[(2 * op) * 36 + ii]; hi = w3[(2 * op + 1) * 36 + ii];
    } else if (i < P_W4) {
        int op = i - P_B3;
        lo = b3[2 * op];            hi = b3[2 * op + 1];
    } else if (i < P_B4) {
        int op = i - P_W4;
        lo = w4[2 * op];            hi = w4[2 * op + 1];
    } else if (i == P_B4) {
        lo = b4[0];                 hi = 0.f;
    }
    g_pack[i] = make_float2(lo, hi);
}

// Vectorized clear: 2 cells (16B) per thread.
__global__ void init_cells(void) {
    int i = blockIdx.x * blockDim.x + threadIdx.x;
    if (i < (K_DIM * N_DIM) / 2)
        *reinterpret_cast<ulonglong2*>(&g_cells[2 * i]) = make_ulonglong2(0ull, 0ull);
}
__global__ void init_out(float* out) {
    int i = blockIdx.x * blockDim.x + threadIdx.x;
    if (i < N_DIM) out[K_DIM + i] = -INFINITY;  // col_max accumulators
}

__device__ __forceinline__ u64 fma2(u64 a, u64 b, u64 c) {
    u64 d;
    asm("fma.rn.f32x2 %0, %1, %2, %3;" : "=l"(d) : "l"(a), "l"(b), "l"(c));
    return d;
}
__device__ __forceinline__ u64 relu2(u64 a) {
    u64 r;
    asm("{\n\t.reg .f32 l, h;\n\t"
        "mov.b64 {l, h}, %1;\n\t"
        "max.f32 l, l, 0f00000000;\n\t"
        "max.f32 h, h, 0f00000000;\n\t"
        "mov.b64 %0, {l, h};\n\t}" : "=l"(r) : "l"(a));
    return r;
}
__device__ __forceinline__ u64 dupf(float v) {
    u64 r;
    asm("mov.b64 %0, {%1, %1};" : "=l"(r) : "f"(v));
    return r;
}
__device__ __forceinline__ u64 dup_lo(u64 p) {
    u64 r;
    asm("{\n\t.reg .f32 l, h;\n\tmov.b64 {l, h}, %1;\n\tmov.b64 %0, {l, l};\n\t}"
        : "=l"(r) : "l"(p));
    return r;
}
__device__ __forceinline__ u64 dup_hi(u64 p) {
    u64 r;
    asm("{\n\t.reg .f32 l, h;\n\tmov.b64 {l, h}, %1;\n\tmov.b64 %0, {h, h};\n\t}"
        : "=l"(r) : "l"(p));
    return r;
}
__device__ __forceinline__ float hadd2(u64 p) {
    float r;
    asm("{\n\t.reg .f32 l, h;\n\tmov.b64 {l, h}, %1;\n\tadd.f32 %0, l, h;\n\t}"
        : "=f"(r) : "l"(p));
    return r;
}
__device__ __forceinline__ u64 mk64(unsigned lo, unsigned hi) {
    return ((u64)hi << 32) | (u64)lo;
}

// ONE point per thread; f32x2 lanes = two adjacent neurons. Weights from the
// constant port (LDC.128 = 4 distinct weights), activations lane-duplicated by
// register MOVs. regs=77 natural -> 6 CTAs/SM. DO NOT perturb launch bounds,
// block size, or loop structure: ptxas's FFMA2 pairing is sensitive to all
// three (measured regressions in r6/r12/r13/r15).
__global__ __launch_bounds__(128, 5) void mlp_scatter_kernel(
    const float* __restrict__ xin, const int* __restrict__ tind)
{
    int m = blockIdx.x * 128 + threadIdx.x;
    if (m >= M_PTS) return;

    const u64* cv = reinterpret_cast<const u64*>(cw);

    // Inputs: scalar per feature, duplicated into both lanes.
    u64 xd[7];
    #pragma unroll
    for (int f = 0; f < 7; ++f)
        xd[f] = dupf(xin[f * M_PTS + m]);

    // ── Layer 1: 7 -> 18 (9 neuron pairs)
    u64 h1[9];
    #pragma unroll
    for (int op = 0; op < 9; ++op) {
        u64 a = cv[P_B1 + op];
        #pragma unroll
        for (int f = 0; f < 7; ++f)
            a = fma2(cv[P_W1 + f * 9 + op], xd[f], a);
        h1[op] = relu2(a);
    }

    // ── Layer 2: 18 -> 36 (18 neuron pairs), i-outer outer-product.
    u64 a2[18];
    #pragma unroll
    for (int op = 0; op < 18; ++op) a2[op] = cv[P_B2 + op];
    #pragma unroll
    for (int ip = 0; ip < 9; ++ip) {
        u64 p = h1[ip];
        #pragma unroll
        for (int half = 0; half < 2; ++half) {
            u64 d = half ? dup_hi(p) : dup_lo(p);
            int i = 2 * ip + half;
            #pragma unroll
            for (int op = 0; op < 18; op += 2) {
                uint4 q = *reinterpret_cast<const uint4*>(&cw[P_W2 + i * 18 + op]);
                a2[op]     = fma2(mk64(q.x, q.y), d, a2[op]);
                a2[op + 1] = fma2(mk64(q.z, q.w), d, a2[op + 1]);
            }
        }
    }
    #pragma unroll
    for (int op = 0; op < 18; ++op) a2[op] = relu2(a2[op]);

    // ── Layer 3+4 fused, single pass.
    u64 v = cv[P_B4];   // (b4, 0): final = lo + hi
    u64 c[18];
    #pragma unroll
    for (int op = 0; op < 18; ++op) c[op] = cv[P_B3 + op];
    #pragma unroll
    for (int ih = 0; ih < 18; ++ih) {
        u64 p = a2[ih];
        #pragma unroll
        for (int half = 0; half < 2; ++half) {
            u64 d = half ? dup_hi(p) : dup_lo(p);
            int i = 2 * ih + half;
            #pragma unroll
            for (int op = 0; op < 18; op += 2) {
                uint4 q = *reinterpret_cast<const uint4*>(&cw[P_W3 + i * 18 + op]);
                c[op]     = fma2(mk64(q.x, q.y), d, c[op]);
                c[op + 1] = fma2(mk64(q.z, q.w), d, c[op + 1]);
            }
        }
    }
    #pragma unroll
    for (int op = 0; op < 18; ++op)
        v = fma2(cv[P_W4 + op], relu2(c[op]), v);

    float val = hadd2(v);

    int r = tind[m];
    int cc = tind[M_PTS + m];
    atomicMax(&g_cells[r * N_DIM + cc],
              (((u64)(unsigned)(m + 1)) << 32) | (u64)__float_as_uint(val));
}

__device__ __forceinline__ float cell_val(u64 k) {
    return (k == 0ull) ? SENTINEL : __uint_as_float((unsigned)(k & 0xFFFFFFFFull));
}

__global__ void row_max_kernel(float* out) {
    int i = blockIdx.x;
    __shared__ float red[256];
    float mx = SENTINEL;
    #pragma unroll
    for (int j = threadIdx.x; j < N_DIM; j += 256)
        mx = fmaxf(mx, cell_val(g_cells[i * N_DIM + j]));
    red[threadIdx.x] = mx;
    __syncthreads();
    #pragma unroll
    for (int s2 = 128; s2 > 0; s2 >>= 1) {
        if (threadIdx.x < s2)
            red[threadIdx.x] = fmaxf(red[threadIdx.x], red[threadIdx.x + s2]);
        __syncthreads();
    }
    if (threadIdx.x == 0) out[i] = red[0];
}

// Order-preserving float atomic max (mixed signs; accumulator init -inf).
__device__ __forceinline__ void atomicMaxFloat(float* addr, float val) {
    if (val >= 0.0f) atomicMax((int*)addr, __float_as_int(val));
    else             atomicMin((unsigned int*)addr, __float_as_uint(val));
}

// blockDim (64,4): 64 cols wide, 64-row strip per blockIdx.y -> 256 blocks.
__global__ void col_max_kernel(float* out) {
    int j = blockIdx.x * 64 + threadIdx.x;
    float mx = SENTINEL;
    if (j < N_DIM) {
        int r0 = blockIdx.y * 64;
        int r1 = min(r0 + 64, K_DIM);
        for (int r = r0 + threadIdx.y; r < r1; r += 4)
            mx = fmaxf(mx, cell_val(g_cells[r * N_DIM + j]));
    }
    __shared__ float red[4][64];
    red[threadIdx.y][threadIdx.x] = mx;
    __syncthreads();
    if (threadIdx.y == 0 && j < N_DIM) {
        float m2 = fmaxf(fmaxf(red[0][threadIdx.x], red[1][threadIdx.x]),
                         fmaxf(red[2][threadIdx.x], red[3][threadIdx.x]));
        atomicMaxFloat(&out[K_DIM + j], m2);
    }
}

extern "C" void kernel_launch(void* const* d_in, const int* in_sizes, int n_in,
                              void* d_out, int out_size) {
    const float* xin = (const float*)d_in[0];
    // d_in[1] = T_out (zeros, unused)
    const int*   tind = (const int*)d_in[2];
    const float* w1 = (const float*)d_in[3];
    const float* b1 = (const float*)d_in[4];
    const float* w2 = (const float*)d_in[5];
    const float* b2 = (const float*)d_in[6];
    const float* w3 = (const float*)d_in[7];
    const float* b3 = (const float*)d_in[8];
    const float* w4 = (const float*)d_in[9];
    const float* b4 = (const float*)d_in[10];
    float* out = (float*)d_out;

    // 1) pack neuron-paired weights into staging buffer
    pack_kernel<<<(P_TOTAL + 255) / 256, 256>>>(w1, b1, w2, b2, w3, b3, w4, b4);

    // 2) D2D async copy into constant memory (graph-capturable memcpy node)
    void* pack_addr = nullptr;
    cudaGetSymbolAddress(&pack_addr, g_pack);
    cudaMemcpyToSymbolAsync(cw, pack_addr, sizeof(float2) * P_TOTAL, 0,
                            cudaMemcpyDeviceToDevice, 0);

    // 3) inits
    init_cells<<<(K_DIM * N_DIM / 2 + 255) / 256, 256>>>();
    init_out<<<(N_DIM + 255) / 256, 256>>>(out);

    // 4) MLP + scatter: ONE point per thread, 128-thread blocks
    mlp_scatter_kernel<<<(M_PTS + 127) / 128, 128>>>(xin, tind);

    // 5) reductions
    row_max_kernel<<<K_DIM, 256>>>(out);
    dim3 cb(64, 4), cg(16, 16);
    col_max_kernel<<<cg, cb>>>(out);
}

// round 17
// speedup vs baseline: 1.5750x; 1.0051x over previous
#include <cuda_runtime.h>
#include <math.h>

#define K_DIM 1000
#define N_DIM 1000
#define M_PTS 900000
#define SENTINEL -9999.0f

typedef unsigned long long u64;

// Scratch grid: packed cells. High 32 bits = (m+1) (scatter order priority,
// last-write-wins like XLA in-order scatter), low 32 bits = float bits of val.
__device__ u64 g_cells[K_DIM * N_DIM];

// ── Packed constant layout (float2 units). f32x2 lanes = neurons (2op, 2op+1),
// weights UNduplicated: every 16B LDC.128 carries 4 distinct weights.
#define P_W1 0
#define P_B1 63
#define P_W2 72
#define P_B2 396
#define P_W3 414
#define P_B3 1062
#define P_W4 1080
#define P_B4 1098
#define P_TOTAL 1100

__constant__ __align__(16) float2 cw[P_TOTAL];
__device__ float2 g_pack[P_TOTAL];

__global__ void pack_kernel(
    const float* __restrict__ w1, const float* __restrict__ b1,
    const float* __restrict__ w2, const float* __restrict__ b2,
    const float* __restrict__ w3, const float* __restrict__ b3,
    const float* __restrict__ w4, const float* __restrict__ b4)
{
    int i = blockIdx.x * blockDim.x + threadIdx.x;
    if (i >= P_TOTAL) return;
    float lo = 0.f, hi = 0.f;
    if (i < P_B1) {
        int f = i / 9, op = i % 9;
        lo = w1[(2 * op) * 7 + f];  hi = w1[(2 * op + 1) * 7 + f];
    } else if (i < P_W2) {
        int op = i - P_B1;
        lo = b1[2 * op];            hi = b1[2 * op + 1];
    } else if (i < P_B2) {
        int j = i - P_W2, ii = j / 18, op = j % 18;
        lo = w2[(2 * op) * 18 + ii]; hi = w2[(2 * op + 1) * 18 + ii];
    } else if (i < P_W3) {
        int op = i - P_B2;
        lo = b2[2 * op];            hi = b2[2 * op + 1];
    } else if (i < P_B3) {
        int j = i - P_W3, ii = j / 18, op = j % 18;
        lo = w3[(2 * op) * 36 + ii]; hi = w3[(2 * op + 1) * 36 + ii];
    } else if (i < P_W4) {
        int op = i - P_B3;
        lo = b3[2 * op];            hi = b3[2 * op + 1];
    } else if (i < P_B4) {
        int op = i - P_W4;
        lo = w4[2 * op];            hi = w4[2 * op + 1];
    } else if (i == P_B4) {
        lo = b4[0];                 hi = 0.f;
    }
    g_pack[i] = make_float2(lo, hi);
}

// Combined init: clears the cell grid (2 cells / 16B per thread) and the
// col_max accumulators (-inf) in one launch — one fewer graph node.
__global__ void init_kernel(float* out) {
    int i = blockIdx.x * blockDim.x + threadIdx.x;
    if (i < (K_DIM * N_DIM) / 2)
        *reinterpret_cast<ulonglong2*>(&g_cells[2 * i]) = make_ulonglong2(0ull, 0ull);
    if (i < N_DIM) out[K_DIM + i] = -INFINITY;
}

__device__ __forceinline__ u64 fma2(u64 a, u64 b, u64 c) {
    u64 d;
    asm("fma.rn.f32x2 %0, %1, %2, %3;" : "=l"(d) : "l"(a), "l"(b), "l"(c));
    return d;
}
__device__ __forceinline__ u64 relu2(u64 a) {
    u64 r;
    asm("{\n\t.reg .f32 l, h;\n\t"
        "mov.b64 {l, h}, %1;\n\t"
        "max.f32 l, l, 0f00000000;\n\t"
        "max.f32 h, h, 0f00000000;\n\t"
        "mov.b64 %0, {l, h};\n\t}" : "=l"(r) : "l"(a));
    return r;
}
__device__ __forceinline__ u64 dupf(float v) {
    u64 r;
    asm("mov.b64 %0, {%1, %1};" : "=l"(r) : "f"(v));
    return r;
}
__device__ __forceinline__ u64 dup_lo(u64 p) {
    u64 r;
    asm("{\n\t.reg .f32 l, h;\n\tmov.b64 {l, h}, %1;\n\tmov.b64 %0, {l, l};\n\t}"
        : "=l"(r) : "l"(p));
    return r;
}
__device__ __forceinline__ u64 dup_hi(u64 p) {
    u64 r;
    asm("{\n\t.reg .f32 l, h;\n\tmov.b64 {l, h}, %1;\n\tmov.b64 %0, {h, h};\n\t}"
        : "=l"(r) : "l"(p));
    return r;
}
__device__ __forceinline__ float hadd2(u64 p) {
    float r;
    asm("{\n\t.reg .f32 l, h;\n\tmov.b64 {l, h}, %1;\n\tadd.f32 %0, l, h;\n\t}"
        : "=f"(r) : "l"(p));
    return r;
}
__device__ __forceinline__ u64 mk64(unsigned lo, unsigned hi) {
    return ((u64)hi << 32) | (u64)lo;
}

// ONE point per thread; f32x2 lanes = two adjacent neurons. Weights from the
// constant port (LDC.128 = 4 distinct weights), activations lane-duplicated by
// register MOVs. regs=77 natural -> 6 CTAs/SM. DO NOT perturb launch bounds,
// block size, or loop structure: ptxas's FFMA2 pairing is sensitive to all
// three (measured regressions in r6/r12/r13/r15).
__global__ __launch_bounds__(128, 5) void mlp_scatter_kernel(
    const float* __restrict__ xin, const int* __restrict__ tind)
{
    int m = blockIdx.x * 128 + threadIdx.x;
    if (m >= M_PTS) return;

    const u64* cv = reinterpret_cast<const u64*>(cw);

    // Inputs: scalar per feature, duplicated into both lanes.
    u64 xd[7];
    #pragma unroll
    for (int f = 0; f < 7; ++f)
        xd[f] = dupf(xin[f * M_PTS + m]);

    // ── Layer 1: 7 -> 18 (9 neuron pairs)
    u64 h1[9];
    #pragma unroll
    for (int op = 0; op < 9; ++op) {
        u64 a = cv[P_B1 + op];
        #pragma unroll
        for (int f = 0; f < 7; ++f)
            a = fma2(cv[P_W1 + f * 9 + op], xd[f], a);
        h1[op] = relu2(a);
    }

    // ── Layer 2: 18 -> 36 (18 neuron pairs), i-outer outer-product.
    u64 a2[18];
    #pragma unroll
    for (int op = 0; op < 18; ++op) a2[op] = cv[P_B2 + op];
    #pragma unroll
    for (int ip = 0; ip < 9; ++ip) {
        u64 p = h1[ip];
        #pragma unroll
        for (int half = 0; half < 2; ++half) {
            u64 d = half ? dup_hi(p) : dup_lo(p);
            int i = 2 * ip + half;
            #pragma unroll
            for (int op = 0; op < 18; op += 2) {
                uint4 q = *reinterpret_cast<const uint4*>(&cw[P_W2 + i * 18 + op]);
                a2[op]     = fma2(mk64(q.x, q.y), d, a2[op]);
                a2[op + 1] = fma2(mk64(q.z, q.w), d, a2[op + 1]);
            }
        }
    }
    #pragma unroll
    for (int op = 0; op < 18; ++op) a2[op] = relu2(a2[op]);

    // ── Layer 3+4 fused, single pass.
    u64 v = cv[P_B4];   // (b4, 0): final = lo + hi
    u64 c[18];
    #pragma unroll
    for (int op = 0; op < 18; ++op) c[op] = cv[P_B3 + op];
    #pragma unroll
    for (int ih = 0; ih < 18; ++ih) {
        u64 p = a2[ih];
        #pragma unroll
        for (int half = 0; half < 2; ++half) {
            u64 d = half ? dup_hi(p) : dup_lo(p);
            int i = 2 * ih + half;
            #pragma unroll
            for (int op = 0; op < 18; op += 2) {
                uint4 q = *reinterpret_cast<const uint4*>(&cw[P_W3 + i * 18 + op]);
                c[op]     = fma2(mk64(q.x, q.y), d, c[op]);
                c[op + 1] = fma2(mk64(q.z, q.w), d, c[op + 1]);
            }
        }
    }
    #pragma unroll
    for (int op = 0; op < 18; ++op)
        v = fma2(cv[P_W4 + op], relu2(c[op]), v);

    float val = hadd2(v);

    int r = tind[m];
    int cc = tind[M_PTS + m];
    atomicMax(&g_cells[r * N_DIM + cc],
              (((u64)(unsigned)(m + 1)) << 32) | (u64)__float_as_uint(val));
}

__device__ __forceinline__ float cell_val(u64 k) {
    return (k == 0ull) ? SENTINEL : __uint_as_float((unsigned)(k & 0xFFFFFFFFull));
}

__global__ void row_max_kernel(float* out) {
    int i = blockIdx.x;
    __shared__ float red[256];
    float mx = SENTINEL;
    #pragma unroll
    for (int j = threadIdx.x; j < N_DIM; j += 256)
        mx = fmaxf(mx, cell_val(g_cells[i * N_DIM + j]));
    red[threadIdx.x] = mx;
    __syncthreads();
    #pragma unroll
    for (int s2 = 128; s2 > 0; s2 >>= 1) {
        if (threadIdx.x < s2)
            red[threadIdx.x] = fmaxf(red[threadIdx.x], red[threadIdx.x + s2]);
        __syncthreads();
    }
    if (threadIdx.x == 0) out[i] = red[0];
}

// Order-preserving float atomic max (mixed signs; accumulator init -inf).
__device__ __forceinline__ void atomicMaxFloat(float* addr, float val) {
    if (val >= 0.0f) atomicMax((int*)addr, __float_as_int(val));
    else             atomicMin((unsigned int*)addr, __float_as_uint(val));
}

// blockDim (64,4): 64 cols wide, 64-row strip per blockIdx.y -> 256 blocks.
__global__ void col_max_kernel(float* out) {
    int j = blockIdx.x * 64 + threadIdx.x;
    float mx = SENTINEL;
    if (j < N_DIM) {
        int r0 = blockIdx.y * 64;
        int r1 = min(r0 + 64, K_DIM);
        for (int r = r0 + threadIdx.y; r < r1; r += 4)
            mx = fmaxf(mx, cell_val(g_cells[r * N_DIM + j]));
    }
    __shared__ float red[4][64];
    red[threadIdx.y][threadIdx.x] = mx;
    __syncthreads();
    if (threadIdx.y == 0 && j < N_DIM) {
        float m2 = fmaxf(fmaxf(red[0][threadIdx.x], red[1][threadIdx.x]),
                         fmaxf(red[2][threadIdx.x], red[3][threadIdx.x]));
        atomicMaxFloat(&out[K_DIM + j], m2);
    }
}

extern "C" void kernel_launch(void* const* d_in, const int* in_sizes, int n_in,
                              void* d_out, int out_size) {
    const float* xin = (const float*)d_in[0];
    // d_in[1] = T_out (zeros, unused)
    const int*   tind = (const int*)d_in[2];
    const float* w1 = (const float*)d_in[3];
    const float* b1 = (const float*)d_in[4];
    const float* w2 = (const float*)d_in[5];
    const float* b2 = (const float*)d_in[6];
    const float* w3 = (const float*)d_in[7];
    const float* b3 = (const float*)d_in[8];
    const float* w4 = (const float*)d_in[9];
    const float* b4 = (const float*)d_in[10];
    float* out = (float*)d_out;

    // 1) pack neuron-paired weights into staging buffer
    pack_kernel<<<(P_TOTAL + 255) / 256, 256>>>(w1, b1, w2, b2, w3, b3, w4, b4);

    // 2) D2D async copy into constant memory (graph-capturable memcpy node)
    void* pack_addr = nullptr;
    cudaGetSymbolAddress(&pack_addr, g_pack);
    cudaMemcpyToSymbolAsync(cw, pack_addr, sizeof(float2) * P_TOTAL, 0,
                            cudaMemcpyDeviceToDevice, 0);

    // 3) combined init (grid clear + col_max accumulators)
    init_kernel<<<(K_DIM * N_DIM / 2 + 255) / 256, 256>>>(out);

    // 4) MLP + scatter: ONE point per thread, 128-thread blocks
    mlp_scatter_kernel<<<(M_PTS + 127) / 128, 128>>>(xin, tind);

    // 5) reductions
    row_max_kernel<<<K_DIM, 256>>>(out);
    dim3 cb(64, 4), cg(16, 16);
    col_max_kernel<<<cg, cb>>>(out);
}